// round 8
// baseline (speedup 1.0000x reference)
#include <cuda_runtime.h>
#include <cuda_fp16.h>
#include <math.h>
#include <cstdint>

#define BB 8
#define TT 512
#define DD 128
#define HH 8

typedef unsigned long long u64;

__device__ __forceinline__ u64 ffma2_(u64 a, u64 b, u64 c) {
    u64 d; asm("fma.rn.f32x2 %0, %1, %2, %3;" : "=l"(d) : "l"(a), "l"(b), "l"(c)); return d;
}
__device__ __forceinline__ float2 unpack2_(u64 v) {
    float2 f; asm("mov.b64 {%0, %1}, %2;" : "=f"(f.x), "=f"(f.y) : "l"(v)); return f;
}

// m16n8k16 f16 MMA, fp32 accumulate (portable PTX, runs on sm_103 HMMA)
__device__ __forceinline__ void mma16816_(float* c, const unsigned* a, const unsigned* b) {
    asm volatile(
        "mma.sync.aligned.m16n8k16.row.col.f32.f16.f16.f32 "
        "{%0,%1,%2,%3}, {%4,%5,%6,%7}, {%8,%9}, {%0,%1,%2,%3};"
        : "+f"(c[0]), "+f"(c[1]), "+f"(c[2]), "+f"(c[3])
        : "r"(a[0]), "r"(a[1]), "r"(a[2]), "r"(a[3]), "r"(b[0]), "r"(b[1]));
}

// Scratch
__device__ float  g_q [BB*HH*TT*DD];          // q[b][h][t][d] fp32
__device__ __half g_vT[(size_t)BB*HH*DD*TT];  // vT[b][h][d][s] fp16
__device__ float  g_o [BB*HH*TT*DD];          // o[b][h][t][d] fp32

// ---------------------------------------------------------------------------
// Kernel 1: QV projection via mma.sync (HMMA).
// Tile 64 (t) x 64 (o). Each 64-o tile is entirely q or entirely v.
// Warp w: m-tile mt=w&3 (16 t-rows), n-group ng=w>>2 (32 o-cols).
// ---------------------------------------------------------------------------
#define QV_SMEM (2*64*136*2)   // xsh + wsh fp16, stride 136

__global__ __launch_bounds__(256) void qv_kernel(const float* __restrict__ x,
                                                 const float* __restrict__ w) {
    extern __shared__ __half smh[];
    __half* xsh = smh;            // 64 x 136
    __half* wsh = smh + 64*136;   // 64 x 136
    __shared__ float bsh[64];

    const int tid = threadIdx.x;
    const int warp = tid >> 5, lane = tid & 31;
    const int g = lane >> 2, tg = lane & 3;
    const int mt = warp & 3, ng = warp >> 2;
    const int m0 = blockIdx.y * 64;   // bt tile
    const int n0 = blockIdx.x * 64;   // o tile

    // stage x tile fp32 -> fp16
    const float4* xg = (const float4*)(x + (size_t)m0*DD);
    for (int i = tid; i < 64*32; i += 256) {
        int r = i >> 5, c4 = i & 31;
        float4 v = xg[i];
        __half2 h0 = __floats2half2_rn(v.x, v.y);
        __half2 h1 = __floats2half2_rn(v.z, v.w);
        uint2 st; st.x = *(unsigned*)&h0; st.y = *(unsigned*)&h1;
        *(uint2*)&xsh[r*136 + c4*4] = st;
    }
    // stage W tile fp32 -> fp16 (gmem row length 129, odd -> scalar loads)
    for (int i = tid; i < 64*64; i += 256) {
        int r = i >> 6, c2 = i & 63;
        const float* wr = w + (size_t)(n0 + r)*129 + c2*2;
        __half2 h = __floats2half2_rn(wr[0], wr[1]);
        *(unsigned*)&wsh[r*136 + c2*2] = *(unsigned*)&h;
    }
    if (tid < 64) bsh[tid] = w[(size_t)(n0 + tid)*129 + 128];
    __syncthreads();

    float oacc[4][4];
#pragma unroll
    for (int nt = 0; nt < 4; nt++)
#pragma unroll
        for (int c = 0; c < 4; c++) oacc[nt][c] = 0.f;

#pragma unroll
    for (int kk = 0; kk < 8; kk++) {
        unsigned af[4];
        const int ar = (mt*16 + g)*136 + kk*16 + tg*2;
        af[0] = *(const unsigned*)&xsh[ar];
        af[1] = *(const unsigned*)&xsh[ar + 8*136];
        af[2] = *(const unsigned*)&xsh[ar + 8];
        af[3] = *(const unsigned*)&xsh[ar + 8*136 + 8];
#pragma unroll
        for (int nt = 0; nt < 4; nt++) {
            const int br = (ng*32 + nt*8 + g)*136 + kk*16 + tg*2;
            unsigned bf[2];
            bf[0] = *(const unsigned*)&wsh[br];
            bf[1] = *(const unsigned*)&wsh[br + 8];
            mma16816_(oacc[nt], af, bf);
        }
    }

    // bias
#pragma unroll
    for (int nt = 0; nt < 4; nt++) {
        const int col = ng*32 + nt*8 + tg*2;
        oacc[nt][0] += bsh[col];     oacc[nt][1] += bsh[col + 1];
        oacc[nt][2] += bsh[col];     oacc[nt][3] += bsh[col + 1];
    }

    const int bi = m0 >> 9, tb = m0 & 511;
    const int cbase = n0 & 255;       // uniform per CTA
    const int hh = n0 >> 8;

    if (cbase < 128) {
        // q tile: fp32 coalesced-ish float2 stores
        float* qg_ = g_q + ((size_t)(bi*HH + hh)*TT + tb)*DD + cbase;
#pragma unroll
        for (int nt = 0; nt < 4; nt++) {
            const int col = ng*32 + nt*8 + tg*2;
            const int r0 = mt*16 + g;
            *(float2*)&qg_[(size_t)r0*DD + col]       = make_float2(oacc[nt][0], oacc[nt][1]);
            *(float2*)&qg_[(size_t)(r0 + 8)*DD + col] = make_float2(oacc[nt][2], oacc[nt][3]);
        }
    } else {
        // v tile: transpose through smem, then coalesced fp16 stores to g_vT
        __syncthreads();               // xsh no longer needed
        __half* vsm = xsh;             // 64 d-rows x 72 (t stride)
#pragma unroll
        for (int nt = 0; nt < 4; nt++) {
            const int dl = ng*32 + nt*8 + tg*2;
            const int r0 = mt*16 + g;
            vsm[dl*72 + r0]           = __float2half(oacc[nt][0]);
            vsm[(dl + 1)*72 + r0]     = __float2half(oacc[nt][1]);
            vsm[dl*72 + r0 + 8]       = __float2half(oacc[nt][2]);
            vsm[(dl + 1)*72 + r0 + 8] = __float2half(oacc[nt][3]);
        }
        __syncthreads();
        __half* vg = g_vT + ((size_t)(bi*HH + hh)*DD + (cbase - 128))*TT + tb;
        for (int i = tid; i < 1024; i += 256) {
            int row = i >> 4, seg = i & 15;
            uint2 val = *(uint2*)&vsm[row*72 + seg*4];
            *(uint2*)&vg[(size_t)row*TT + seg*4] = val;
        }
    }
}

// ---------------------------------------------------------------------------
// Kernel 2: fused L1 attention. fp32 distance + mma.sync (HMMA) P@V.
// (unchanged from R6)
// ---------------------------------------------------------------------------
#define SSTRIDE 520
#define ATTN_SMEM 200704
#define OFF_Q  133120
#define OFF_K  166912
#define OFF_VT 133120

__global__ __launch_bounds__(256) void attn_kernel(const float* __restrict__ x,
                                                   const float* __restrict__ wk,
                                                   const float* __restrict__ msk) {
    extern __shared__ char smc[];
    float* Ssh = (float*)smc;
    float* qsh = (float*)(smc + OFF_Q);
    float* ksh = (float*)(smc + OFF_K);
    __shared__ float wksh[128];

    const int b  = blockIdx.z, h = blockIdx.y;
    const int t0 = blockIdx.x * 64;
    const int tid = threadIdx.x;
    const int tx  = tid & 15, ty = tid >> 4;

    if (tid < 128) wksh[tid] = wk[h*DD + tid];

    // stage q tile
    const float4* qg = (const float4*)(g_q + (((size_t)(b*HH + h))*TT + t0)*DD);
    for (int i = tid; i < 64*32; i += 256) {
        int r = i >> 5, c4 = i & 31;
        *(float4*)&qsh[r*132 + c4*4] = qg[i];
    }
    __syncthreads();

    const float NEG_ISQ = -0.08838834764831845f;  // -1/sqrt(128)

    // ---------------- Phase 1: score tiles (fp32, at the fma-pipe floor) ----
    float4 kreg[8];
    {
        const float4* xg = (const float4*)(x + ((size_t)b*TT)*DD);
#pragma unroll
        for (int u = 0; u < 8; u++) kreg[u] = xg[tid + u*256];
    }

    for (int s0 = 0; s0 < TT; s0 += 64) {
#pragma unroll
        for (int u = 0; u < 8; u++) {
            int i = tid + u*256;
            int r = i >> 5, c4 = i & 31;
            float4 v = kreg[u];
            v.x *= wksh[c4*4 + 0]; v.y *= wksh[c4*4 + 1];
            v.z *= wksh[c4*4 + 2]; v.w *= wksh[c4*4 + 3];
            *(float4*)&ksh[r*132 + c4*4] = v;
        }
        __syncthreads();

        if (s0 + 64 < TT) {
            const float4* xg = (const float4*)(x + ((size_t)b*TT + s0 + 64)*DD);
#pragma unroll
            for (int u = 0; u < 8; u++) kreg[u] = xg[tid + u*256];
        }

        float acc[4][4];
#pragma unroll
        for (int i = 0; i < 4; i++)
#pragma unroll
            for (int j = 0; j < 4; j++) acc[i][j] = 0.f;

#pragma unroll 4
        for (int d = 0; d < 128; d += 4) {
            float4 qv[4], kv[4];
#pragma unroll
            for (int i = 0; i < 4; i++) qv[i] = *(const float4*)&qsh[(ty*4 + i)*132 + d];
#pragma unroll
            for (int j = 0; j < 4; j++) kv[j] = *(const float4*)&ksh[(tx + 16*j)*132 + d];
#pragma unroll
            for (int i = 0; i < 4; i++)
#pragma unroll
                for (int j = 0; j < 4; j++) {
                    acc[i][j] += fabsf(qv[i].x - kv[j].x) + fabsf(qv[i].y - kv[j].y)
                               + fabsf(qv[i].z - kv[j].z) + fabsf(qv[i].w - kv[j].w);
                }
        }
#pragma unroll
        for (int i = 0; i < 4; i++)
#pragma unroll
            for (int j = 0; j < 4; j++)
                Ssh[(ty*4 + i)*SSTRIDE + s0 + tx + 16*j] = acc[i][j] * NEG_ISQ;
        __syncthreads();
    }

    // ---------------- Phase 2: row softmax + mask ----------------
    const int warp = tid >> 5, lane = tid & 31;
    for (int r = warp; r < 64; r += 8) {
        float* row = Ssh + r*SSTRIDE;
        float vals[16];
        float m = -1e30f;
#pragma unroll
        for (int i = 0; i < 16; i++) { vals[i] = row[lane + i*32]; m = fmaxf(m, vals[i]); }
#pragma unroll
        for (int o = 16; o > 0; o >>= 1) m = fmaxf(m, __shfl_xor_sync(0xffffffffu, m, o));
        float sum = 0.f;
#pragma unroll
        for (int i = 0; i < 16; i++) { vals[i] = __expf(vals[i] - m); sum += vals[i]; }
#pragma unroll
        for (int o = 16; o > 0; o >>= 1) sum += __shfl_xor_sync(0xffffffffu, sum, o);
        float inv = 1.f / sum;
        const float* mrow = msk + ((size_t)(h*TT + t0 + r))*TT;
#pragma unroll
        for (int i = 0; i < 16; i++)
            row[lane + i*32] = vals[i] * inv * mrow[lane + i*32];
    }
    __syncthreads();

    // ---------------- Phase 3: O = P @ V via mma.sync ----------------
    __half* vTsh = (__half*)(smc + OFF_VT);
    const __half* vTg = g_vT + ((size_t)(b*HH + h))*DD*TT;
    const int mt = warp & 3, ng = warp >> 2;
    const int g = lane >> 2, tg = lane & 3;

    float oacc[8][4];
#pragma unroll
    for (int nt = 0; nt < 8; nt++)
#pragma unroll
        for (int c = 0; c < 4; c++) oacc[nt][c] = 0.f;

    for (int sc = 0; sc < 4; sc++) {
        const int s0 = sc * 128;
        for (int i = tid; i < 2048; i += 256) {
            int r = i >> 4, kg = i & 15;
            uint4 val = *(const uint4*)(vTg + (size_t)r*TT + s0 + kg*8);
            *(uint4*)&vTsh[r*136 + kg*8] = val;
        }
        __syncthreads();

#pragma unroll
        for (int kk = 0; kk < 8; kk++) {
            const int ar = (mt*16 + g)*SSTRIDE + s0 + kk*16 + tg*2;
            float2 a01 = *(const float2*)&Ssh[ar];
            float2 a23 = *(const float2*)&Ssh[ar + 8*SSTRIDE];
            float2 a45 = *(const float2*)&Ssh[ar + 8];
            float2 a67 = *(const float2*)&Ssh[ar + 8*SSTRIDE + 8];
            unsigned af[4];
            __half2 h0 = __floats2half2_rn(a01.x, a01.y); af[0] = *(unsigned*)&h0;
            __half2 h1 = __floats2half2_rn(a23.x, a23.y); af[1] = *(unsigned*)&h1;
            __half2 h2 = __floats2half2_rn(a45.x, a45.y); af[2] = *(unsigned*)&h2;
            __half2 h3 = __floats2half2_rn(a67.x, a67.y); af[3] = *(unsigned*)&h3;

            const int kb = kk*16 + tg*2;
#pragma unroll
            for (int nt = 0; nt < 8; nt++) {
                int row = ng*64 + nt*8 + g;
                unsigned bf[2];
                bf[0] = *(const unsigned*)&vTsh[row*136 + kb];
                bf[1] = *(const unsigned*)&vTsh[row*136 + kb + 8];
                mma16816_(oacc[nt], af, bf);
            }
        }
        __syncthreads();
    }

    float* og = g_o + (((size_t)(b*HH + h))*TT + t0)*DD;
#pragma unroll
    for (int nt = 0; nt < 8; nt++) {
        int d = ng*64 + nt*8 + tg*2;
        int r0 = mt*16 + g;
        *(float2*)&og[(size_t)r0*DD + d]       = make_float2(oacc[nt][0], oacc[nt][1]);
        *(float2*)&og[(size_t)(r0 + 8)*DD + d] = make_float2(oacc[nt][2], oacc[nt][3]);
    }
}

// ---------------------------------------------------------------------------
// Kernel 3: head-reduce + quickGELU + fanout + residual (unchanged)
// ---------------------------------------------------------------------------
__global__ __launch_bounds__(256) void final_kernel(const float* __restrict__ x,
                                                    const float* __restrict__ fw,
                                                    float* __restrict__ out) {
    extern __shared__ float sm[];
    float* Wsh  = sm;            // 128*130
    float* yosh = sm + 128*130;  // 16*128

    const int b = blockIdx.y, t0 = blockIdx.x * 16;
    const int tid = threadIdx.x;

    for (int i = tid; i < 128*129; i += 256) {
        int r = i / 129, c = i - r*129;
        Wsh[r*130 + c] = fw[i];
    }

    for (int i = tid; i < 16*128; i += 256) {
        int r = i >> 7, dd = i & 127;
        float bo = 0.f;
#pragma unroll
        for (int h = 0; h < HH; h++)
            bo += g_o[(((size_t)(b*HH + h))*TT + t0 + r)*DD + dd];
        float z  = bo + 4.5f;
        float sg = 1.f / (1.f + __expf(-1.702f * z));
        yosh[r*128 + dd] = z*sg - 4.5f;
    }
    __syncthreads();

    const int o = tid & 127, half = tid >> 7;
    u64 acc2[8];
#pragma unroll
    for (int rr = 0; rr < 8; rr++) acc2[rr] = 0ULL;

#pragma unroll 4
    for (int i = 0; i < 128; i += 2) {
        u64 w2 = *(const u64*)&Wsh[o*130 + i];
#pragma unroll
        for (int rr = 0; rr < 8; rr++)
            acc2[rr] = ffma2_(w2, *(const u64*)&yosh[(half*8 + rr)*128 + i], acc2[rr]);
    }
    float bias = Wsh[o*130 + 128];
#pragma unroll
    for (int rr = 0; rr < 8; rr++) {
        int t = t0 + half*8 + rr;
        size_t idx = ((size_t)b*TT + t)*DD + o;
        float2 f = unpack2_(acc2[rr]);
        out[idx] = x[idx] + f.x + f.y + bias;
    }
}

// ---------------------------------------------------------------------------
extern "C" void kernel_launch(void* const* d_in, const int* in_sizes, int n_in,
                              void* d_out, int out_size) {
    const float* x   = (const float*)d_in[0];
    const float* msk = (const float*)d_in[1];
    const float* wqv = (const float*)d_in[2];
    const float* wk  = (const float*)d_in[3];
    const float* fw  = (const float*)d_in[4];
    float* out = (float*)d_out;

    cudaFuncSetAttribute(qv_kernel,    cudaFuncAttributeMaxDynamicSharedMemorySize,
                         QV_SMEM);
    cudaFuncSetAttribute(attn_kernel,  cudaFuncAttributeMaxDynamicSharedMemorySize,
                         ATTN_SMEM);
    cudaFuncSetAttribute(final_kernel, cudaFuncAttributeMaxDynamicSharedMemorySize,
                         (128*130 + 16*128) * 4);

    qv_kernel<<<dim3(32, 64), 256, QV_SMEM>>>(x, wqv);
    attn_kernel<<<dim3(TT/64, HH, BB), 256, ATTN_SMEM>>>(x, wk, msk);
    final_kernel<<<dim3(TT/16, BB), 256, (128*130 + 16*128) * 4>>>(x, fw, out);
}

// round 9
// speedup vs baseline: 1.8050x; 1.8050x over previous
#include <cuda_runtime.h>
#include <cuda_fp16.h>
#include <math.h>
#include <cstdint>

#define BB 8
#define TT 512
#define DD 128
#define HH 8

typedef unsigned long long u64;

__device__ __forceinline__ u64 ffma2_(u64 a, u64 b, u64 c) {
    u64 d; asm("fma.rn.f32x2 %0, %1, %2, %3;" : "=l"(d) : "l"(a), "l"(b), "l"(c)); return d;
}
__device__ __forceinline__ float2 unpack2_(u64 v) {
    float2 f; asm("mov.b64 {%0, %1}, %2;" : "=f"(f.x), "=f"(f.y) : "l"(v)); return f;
}

// m16n8k16 f16 MMA, fp32 accumulate (portable PTX, runs on sm_103 HMMA)
__device__ __forceinline__ void mma16816_(float* c, const unsigned* a, const unsigned* b) {
    asm volatile(
        "mma.sync.aligned.m16n8k16.row.col.f32.f16.f16.f32 "
        "{%0,%1,%2,%3}, {%4,%5,%6,%7}, {%8,%9}, {%0,%1,%2,%3};"
        : "+f"(c[0]), "+f"(c[1]), "+f"(c[2]), "+f"(c[3])
        : "r"(a[0]), "r"(a[1]), "r"(a[2]), "r"(a[3]), "r"(b[0]), "r"(b[1]));
}

// |a-b| on fp16x2: HSUB2 (fma pipe) + LOP3 (alu pipe)
__device__ __forceinline__ __half2 habsdiff2_(unsigned a, unsigned b) {
    __half2 d = __hsub2(*(__half2*)&a, *(__half2*)&b);
    unsigned u = (*(unsigned*)&d) & 0x7FFF7FFFu;
    return *(__half2*)&u;
}

// Scratch
__device__ float  g_q [BB*HH*TT*DD];          // q[b][h][t][d] fp32
__device__ __half g_vT[(size_t)BB*HH*DD*TT];  // vT[b][h][d][s] fp16
__device__ float  g_o [BB*HH*TT*DD];          // o[b][h][t][d] fp32

// ---------------------------------------------------------------------------
// Kernel 1: QV projection via mma.sync (HMMA). (R8 version, 45us measured)
// ---------------------------------------------------------------------------
#define QV_SMEM (2*64*136*2)

__global__ __launch_bounds__(256) void qv_kernel(const float* __restrict__ x,
                                                 const float* __restrict__ w) {
    extern __shared__ __half smh[];
    __half* xsh = smh;            // 64 x 136
    __half* wsh = smh + 64*136;   // 64 x 136
    __shared__ float bsh[64];

    const int tid = threadIdx.x;
    const int warp = tid >> 5, lane = tid & 31;
    const int g = lane >> 2, tg = lane & 3;
    const int mt = warp & 3, ng = warp >> 2;
    const int m0 = blockIdx.y * 64;
    const int n0 = blockIdx.x * 64;

    const float4* xg = (const float4*)(x + (size_t)m0*DD);
    for (int i = tid; i < 64*32; i += 256) {
        int r = i >> 5, c4 = i & 31;
        float4 v = xg[i];
        __half2 h0 = __floats2half2_rn(v.x, v.y);
        __half2 h1 = __floats2half2_rn(v.z, v.w);
        uint2 st; st.x = *(unsigned*)&h0; st.y = *(unsigned*)&h1;
        *(uint2*)&xsh[r*136 + c4*4] = st;
    }
    for (int i = tid; i < 64*64; i += 256) {
        int r = i >> 6, c2 = i & 63;
        const float* wr = w + (size_t)(n0 + r)*129 + c2*2;
        __half2 h = __floats2half2_rn(wr[0], wr[1]);
        *(unsigned*)&wsh[r*136 + c2*2] = *(unsigned*)&h;
    }
    if (tid < 64) bsh[tid] = w[(size_t)(n0 + tid)*129 + 128];
    __syncthreads();

    float oacc[4][4];
#pragma unroll
    for (int nt = 0; nt < 4; nt++)
#pragma unroll
        for (int c = 0; c < 4; c++) oacc[nt][c] = 0.f;

#pragma unroll
    for (int kk = 0; kk < 8; kk++) {
        unsigned af[4];
        const int ar = (mt*16 + g)*136 + kk*16 + tg*2;
        af[0] = *(const unsigned*)&xsh[ar];
        af[1] = *(const unsigned*)&xsh[ar + 8*136];
        af[2] = *(const unsigned*)&xsh[ar + 8];
        af[3] = *(const unsigned*)&xsh[ar + 8*136 + 8];
#pragma unroll
        for (int nt = 0; nt < 4; nt++) {
            const int br = (ng*32 + nt*8 + g)*136 + kk*16 + tg*2;
            unsigned bf[2];
            bf[0] = *(const unsigned*)&wsh[br];
            bf[1] = *(const unsigned*)&wsh[br + 8];
            mma16816_(oacc[nt], af, bf);
        }
    }

#pragma unroll
    for (int nt = 0; nt < 4; nt++) {
        const int col = ng*32 + nt*8 + tg*2;
        oacc[nt][0] += bsh[col];     oacc[nt][1] += bsh[col + 1];
        oacc[nt][2] += bsh[col];     oacc[nt][3] += bsh[col + 1];
    }

    const int bi = m0 >> 9, tb = m0 & 511;
    const int cbase = n0 & 255;
    const int hh = n0 >> 8;

    if (cbase < 128) {
        float* qg_ = g_q + ((size_t)(bi*HH + hh)*TT + tb)*DD + cbase;
#pragma unroll
        for (int nt = 0; nt < 4; nt++) {
            const int col = ng*32 + nt*8 + tg*2;
            const int r0 = mt*16 + g;
            *(float2*)&qg_[(size_t)r0*DD + col]       = make_float2(oacc[nt][0], oacc[nt][1]);
            *(float2*)&qg_[(size_t)(r0 + 8)*DD + col] = make_float2(oacc[nt][2], oacc[nt][3]);
        }
    } else {
        __syncthreads();
        __half* vsm = xsh;             // 64 d-rows x 72 (t stride)
#pragma unroll
        for (int nt = 0; nt < 4; nt++) {
            const int dl = ng*32 + nt*8 + tg*2;
            const int r0 = mt*16 + g;
            vsm[dl*72 + r0]           = __float2half(oacc[nt][0]);
            vsm[(dl + 1)*72 + r0]     = __float2half(oacc[nt][1]);
            vsm[dl*72 + r0 + 8]       = __float2half(oacc[nt][2]);
            vsm[(dl + 1)*72 + r0 + 8] = __float2half(oacc[nt][3]);
        }
        __syncthreads();
        __half* vg = g_vT + ((size_t)(bi*HH + hh)*DD + (cbase - 128))*TT + tb;
        for (int i = tid; i < 1024; i += 256) {
            int row = i >> 4, seg = i & 15;
            uint2 val = *(uint2*)&vsm[row*72 + seg*4];
            *(uint2*)&vg[(size_t)row*TT + seg*4] = val;
        }
    }
}

// ---------------------------------------------------------------------------
// Kernel 2: fused L1 attention. fp16 HSUB2/HADD2 distance (flush every 64 d)
// + mma.sync (HMMA) P@V.
// smem (bytes):
//   [0,133120)        Ssh f32 64 x 520
//   [133120,150528)   qsh fp16 64x136     | phase3 vTsh fp16 128x136 overlays
//   [150528,167936)   ksh fp16 64x136     |   [133120,167936)
// ---------------------------------------------------------------------------
#define SSTRIDE 520
#define OFF_QH 133120
#define OFF_KH 150528
#define OFF_VT 133120
#define ATTN_SMEM 167936

__global__ __launch_bounds__(256) void attn_kernel(const float* __restrict__ x,
                                                   const float* __restrict__ wk,
                                                   const float* __restrict__ msk) {
    extern __shared__ char smc[];
    float*  Ssh = (float*)smc;
    __half* qsh = (__half*)(smc + OFF_QH);
    __half* ksh = (__half*)(smc + OFF_KH);
    __shared__ float wksh[128];

    const int b  = blockIdx.z, h = blockIdx.y;
    const int t0 = blockIdx.x * 64;
    const int tid = threadIdx.x;
    const int tx  = tid & 15, ty = tid >> 4;

    if (tid < 128) wksh[tid] = wk[h*DD + tid];

    // stage q tile fp32 -> fp16
    const float4* qg = (const float4*)(g_q + (((size_t)(b*HH + h))*TT + t0)*DD);
    for (int i = tid; i < 64*32; i += 256) {
        int r = i >> 5, c4 = i & 31;
        float4 v = qg[i];
        __half2 h0 = __floats2half2_rn(v.x, v.y);
        __half2 h1 = __floats2half2_rn(v.z, v.w);
        uint2 st; st.x = *(unsigned*)&h0; st.y = *(unsigned*)&h1;
        *(uint2*)&qsh[r*136 + c4*4] = st;
    }
    __syncthreads();

    const float NEG_ISQ = -0.08838834764831845f;  // -1/sqrt(128)

    // ---------------- Phase 1: score tiles (fp16 absdiff) ----------------
    float4 kreg[8];
    {
        const float4* xg = (const float4*)(x + ((size_t)b*TT)*DD);
#pragma unroll
        for (int u = 0; u < 8; u++) kreg[u] = xg[tid + u*256];
    }

    for (int s0 = 0; s0 < TT; s0 += 64) {
        // stage k = x*wk as fp16
#pragma unroll
        for (int u = 0; u < 8; u++) {
            int i = tid + u*256;
            int r = i >> 5, c4 = i & 31;
            float4 v = kreg[u];
            v.x *= wksh[c4*4 + 0]; v.y *= wksh[c4*4 + 1];
            v.z *= wksh[c4*4 + 2]; v.w *= wksh[c4*4 + 3];
            __half2 h0 = __floats2half2_rn(v.x, v.y);
            __half2 h1 = __floats2half2_rn(v.z, v.w);
            uint2 st; st.x = *(unsigned*)&h0; st.y = *(unsigned*)&h1;
            *(uint2*)&ksh[r*136 + c4*4] = st;
        }
        __syncthreads();

        if (s0 + 64 < TT) {
            const float4* xg = (const float4*)(x + ((size_t)b*TT + s0 + 64)*DD);
#pragma unroll
            for (int u = 0; u < 8; u++) kreg[u] = xg[tid + u*256];
        }

        float facc[4][4];
#pragma unroll
        for (int i = 0; i < 4; i++)
#pragma unroll
            for (int j = 0; j < 4; j++) facc[i][j] = 0.f;

        // two 64-d halves, fp16 accumulate inside, fp32 flush at the end
#pragma unroll
        for (int hf = 0; hf < 2; hf++) {
            __half2 hacc[4][4];
            const __half2 hz = __float2half2_rn(0.f);
#pragma unroll
            for (int i = 0; i < 4; i++)
#pragma unroll
                for (int j = 0; j < 4; j++) hacc[i][j] = hz;

#pragma unroll
            for (int dp = 0; dp < 64; dp += 8) {
                const int d = hf*64 + dp;
                uint4 qv[4], kv[4];
#pragma unroll
                for (int i = 0; i < 4; i++) qv[i] = *(const uint4*)&qsh[(ty*4 + i)*136 + d];
#pragma unroll
                for (int j = 0; j < 4; j++) kv[j] = *(const uint4*)&ksh[(tx + 16*j)*136 + d];
#pragma unroll
                for (int i = 0; i < 4; i++)
#pragma unroll
                    for (int j = 0; j < 4; j++) {
                        __half2 a = hacc[i][j];
                        a = __hadd2(a, habsdiff2_(qv[i].x, kv[j].x));
                        a = __hadd2(a, habsdiff2_(qv[i].y, kv[j].y));
                        a = __hadd2(a, habsdiff2_(qv[i].z, kv[j].z));
                        a = __hadd2(a, habsdiff2_(qv[i].w, kv[j].w));
                        hacc[i][j] = a;
                    }
            }
            // flush (2 cvt + 2 fadd per acc; 12% overhead at this granularity)
#pragma unroll
            for (int i = 0; i < 4; i++)
#pragma unroll
                for (int j = 0; j < 4; j++) {
                    float2 f = __half22float2(hacc[i][j]);
                    facc[i][j] += f.x;
                    facc[i][j] += f.y;
                }
        }

#pragma unroll
        for (int i = 0; i < 4; i++)
#pragma unroll
            for (int j = 0; j < 4; j++)
                Ssh[(ty*4 + i)*SSTRIDE + s0 + tx + 16*j] = facc[i][j] * NEG_ISQ;
        __syncthreads();
    }

    // ---------------- Phase 2: row softmax + mask ----------------
    const int warp = tid >> 5, lane = tid & 31;
    for (int r = warp; r < 64; r += 8) {
        float* row = Ssh + r*SSTRIDE;
        float vals[16];
        float m = -1e30f;
#pragma unroll
        for (int i = 0; i < 16; i++) { vals[i] = row[lane + i*32]; m = fmaxf(m, vals[i]); }
#pragma unroll
        for (int o = 16; o > 0; o >>= 1) m = fmaxf(m, __shfl_xor_sync(0xffffffffu, m, o));
        float sum = 0.f;
#pragma unroll
        for (int i = 0; i < 16; i++) { vals[i] = __expf(vals[i] - m); sum += vals[i]; }
#pragma unroll
        for (int o = 16; o > 0; o >>= 1) sum += __shfl_xor_sync(0xffffffffu, sum, o);
        float inv = 1.f / sum;
        const float* mrow = msk + ((size_t)(h*TT + t0 + r))*TT;
#pragma unroll
        for (int i = 0; i < 16; i++)
            row[lane + i*32] = vals[i] * inv * mrow[lane + i*32];
    }
    __syncthreads();

    // ---------------- Phase 3: O = P @ V via mma.sync ----------------
    __half* vTsh = (__half*)(smc + OFF_VT);
    const __half* vTg = g_vT + ((size_t)(b*HH + h))*DD*TT;
    const int mt = warp & 3, ng = warp >> 2;
    const int g = lane >> 2, tg = lane & 3;

    float oacc[8][4];
#pragma unroll
    for (int nt = 0; nt < 8; nt++)
#pragma unroll
        for (int c = 0; c < 4; c++) oacc[nt][c] = 0.f;

    for (int sc = 0; sc < 4; sc++) {
        const int s0 = sc * 128;
        for (int i = tid; i < 2048; i += 256) {
            int r = i >> 4, kg = i & 15;
            uint4 val = *(const uint4*)(vTg + (size_t)r*TT + s0 + kg*8);
            *(uint4*)&vTsh[r*136 + kg*8] = val;
        }
        __syncthreads();

#pragma unroll
        for (int kk = 0; kk < 8; kk++) {
            const int ar = (mt*16 + g)*SSTRIDE + s0 + kk*16 + tg*2;
            float2 a01 = *(const float2*)&Ssh[ar];
            float2 a23 = *(const float2*)&Ssh[ar + 8*SSTRIDE];
            float2 a45 = *(const float2*)&Ssh[ar + 8];
            float2 a67 = *(const float2*)&Ssh[ar + 8*SSTRIDE + 8];
            unsigned af[4];
            __half2 h0 = __floats2half2_rn(a01.x, a01.y); af[0] = *(unsigned*)&h0;
            __half2 h1 = __floats2half2_rn(a23.x, a23.y); af[1] = *(unsigned*)&h1;
            __half2 h2 = __floats2half2_rn(a45.x, a45.y); af[2] = *(unsigned*)&h2;
            __half2 h3 = __floats2half2_rn(a67.x, a67.y); af[3] = *(unsigned*)&h3;

            const int kb = kk*16 + tg*2;
#pragma unroll
            for (int nt = 0; nt < 8; nt++) {
                int row = ng*64 + nt*8 + g;
                unsigned bf[2];
                bf[0] = *(const unsigned*)&vTsh[row*136 + kb];
                bf[1] = *(const unsigned*)&vTsh[row*136 + kb + 8];
                mma16816_(oacc[nt], af, bf);
            }
        }
        __syncthreads();
    }

    float* og = g_o + (((size_t)(b*HH + h))*TT + t0)*DD;
#pragma unroll
    for (int nt = 0; nt < 8; nt++) {
        int d = ng*64 + nt*8 + tg*2;
        int r0 = mt*16 + g;
        *(float2*)&og[(size_t)r0*DD + d]       = make_float2(oacc[nt][0], oacc[nt][1]);
        *(float2*)&og[(size_t)(r0 + 8)*DD + d] = make_float2(oacc[nt][2], oacc[nt][3]);
    }
}

// ---------------------------------------------------------------------------
// Kernel 3: head-reduce + quickGELU + fanout + residual (unchanged)
// ---------------------------------------------------------------------------
__global__ __launch_bounds__(256) void final_kernel(const float* __restrict__ x,
                                                    const float* __restrict__ fw,
                                                    float* __restrict__ out) {
    extern __shared__ float sm[];
    float* Wsh  = sm;            // 128*130
    float* yosh = sm + 128*130;  // 16*128

    const int b = blockIdx.y, t0 = blockIdx.x * 16;
    const int tid = threadIdx.x;

    for (int i = tid; i < 128*129; i += 256) {
        int r = i / 129, c = i - r*129;
        Wsh[r*130 + c] = fw[i];
    }

    for (int i = tid; i < 16*128; i += 256) {
        int r = i >> 7, dd = i & 127;
        float bo = 0.f;
#pragma unroll
        for (int h = 0; h < HH; h++)
            bo += g_o[(((size_t)(b*HH + h))*TT + t0 + r)*DD + dd];
        float z  = bo + 4.5f;
        float sg = 1.f / (1.f + __expf(-1.702f * z));
        yosh[r*128 + dd] = z*sg - 4.5f;
    }
    __syncthreads();

    const int o = tid & 127, half = tid >> 7;
    u64 acc2[8];
#pragma unroll
    for (int rr = 0; rr < 8; rr++) acc2[rr] = 0ULL;

#pragma unroll 4
    for (int i = 0; i < 128; i += 2) {
        u64 w2 = *(const u64*)&Wsh[o*130 + i];
#pragma unroll
        for (int rr = 0; rr < 8; rr++)
            acc2[rr] = ffma2_(w2, *(const u64*)&yosh[(half*8 + rr)*128 + i], acc2[rr]);
    }
    float bias = Wsh[o*130 + 128];
#pragma unroll
    for (int rr = 0; rr < 8; rr++) {
        int t = t0 + half*8 + rr;
        size_t idx = ((size_t)b*TT + t)*DD + o;
        float2 f = unpack2_(acc2[rr]);
        out[idx] = x[idx] + f.x + f.y + bias;
    }
}

// ---------------------------------------------------------------------------
extern "C" void kernel_launch(void* const* d_in, const int* in_sizes, int n_in,
                              void* d_out, int out_size) {
    const float* x   = (const float*)d_in[0];
    const float* msk = (const float*)d_in[1];
    const float* wqv = (const float*)d_in[2];
    const float* wk  = (const float*)d_in[3];
    const float* fw  = (const float*)d_in[4];
    float* out = (float*)d_out;

    cudaFuncSetAttribute(qv_kernel,    cudaFuncAttributeMaxDynamicSharedMemorySize,
                         QV_SMEM);
    cudaFuncSetAttribute(attn_kernel,  cudaFuncAttributeMaxDynamicSharedMemorySize,
                         ATTN_SMEM);
    cudaFuncSetAttribute(final_kernel, cudaFuncAttributeMaxDynamicSharedMemorySize,
                         (128*130 + 16*128) * 4);

    qv_kernel<<<dim3(32, 64), 256, QV_SMEM>>>(x, wqv);
    attn_kernel<<<dim3(TT/64, HH, BB), 256, ATTN_SMEM>>>(x, wk, msk);
    final_kernel<<<dim3(TT/16, BB), 256, (128*130 + 16*128) * 4>>>(x, fw, out);
}